// round 13
// baseline (speedup 1.0000x reference)
#include <cuda_runtime.h>
#include <cstddef>
#include <cstdint>

// Croston's method — fused kernel, round 11.
// 64-thread blocks, one row per block, cp.async staging.
// Affine map tracked as (A,Bz,D,F) only; C and E are derived via the
// invariant  C = A*kc*[A!=1],  E = [A==1]  (kc = a/(1-a), om<1 so A!=1
// iff any nonzero was absorbed). Inclusive Kogge-Stone scan (4 shfls per
// round, no exclusive shift); thread t replays segment (t+1)&63, thread 63
// replays segment 0 with the raw initial state.

static constexpr int T_LEN   = 2048;
static constexpr int SEGS    = 64;
static constexpr int B_ROWS  = 8192;
static constexpr int THREADS = 64;
static constexpr int S4      = 9;          // float4 per segment slot (8 data + pad)

__device__ __forceinline__ uint32_t smem_u32(const void* p) {
    uint32_t a;
    asm("{ .reg .u64 t; cvta.to.shared.u64 t, %1; cvt.u32.u64 %0, t; }"
        : "=r"(a) : "l"(p));
    return a;
}

__global__ __launch_bounds__(THREADS, 24) void croston_fused_kernel(
    const float* __restrict__ x,
    const float* __restrict__ alpha,
    const float* __restrict__ Z0,
    const float* __restrict__ V0,
    const float* __restrict__ q0,
    float* __restrict__ out)
{
    __shared__ float4 sx[SEGS * S4];   // 9216 B
    __shared__ float  swtot[4];        // lower-warp (A,Bz,D,F) total

    int tx = threadIdx.x;              // == segment index
    int b  = blockIdx.x;               // row

    // ── 1. staging via cp.async: 512 float4, slot = p + (p>>3) ──
    {
        const float4* gx = reinterpret_cast<const float4*>(x + (size_t)b * T_LEN);
        #pragma unroll
        for (int i = 0; i < 8; i++) {
            int p = i * THREADS + tx;
            uint32_t dst = smem_u32(&sx[p + (p >> 3)]);
            asm volatile("cp.async.cg.shared.global [%0], [%1], 16;\n"
                         :: "r"(dst), "l"(gx + p));
        }
        asm volatile("cp.async.commit_group;\n");
    }

    float a   = __ldg(alpha);
    float kc  = __fdividef(a, 1.0f - a);   // a/(1-a)

    int lane = tx & 31;
    int half = tx >> 5;                // 0: segs 0..31, 1: segs 32..63

    float Zi = __ldg(Z0 + b);
    float Vi = __ldg(V0 + b);
    float qi = __ldg(q0 + b);

    asm volatile("cp.async.wait_group 0;\n" ::: "memory");
    __syncthreads();

    // ── 2. build affine map (Z,V,q) -> (A*Z+Bz, A*V+C*q+D, E*q+F) ──
    // select-free: nzf = min(x,1) in {0,1};  q' = ez*q + 1 with ez = 1-nzf
    float A = 1.0f, Bz = 0.0f, D = 0.0f, F = 0.0f;
    {
        const float4* seg4 = &sx[tx * S4];
        #pragma unroll
        for (int i = 0; i < 8; i++) {
            float4 v = seg4[i];
            float xv[4] = {v.x, v.y, v.z, v.w};
            #pragma unroll
            for (int j = 0; j < 4; j++) {
                float xt  = xv[j];
                float nzf = fminf(xt, 1.0f);
                float anz = a * nzf;
                float ez  = 1.0f - nzf;
                Bz = fmaf(anz, xt - Bz, Bz);
                D  = fmaf(anz, F  - D,  D);   // uses pre-update F
                A  = fmaf(anz, -A, A);
                F  = fmaf(ez, F, 1.0f);
            }
        }
    }

    // ── 3. Kogge-Stone inclusive scan (combine: mine ∘ prev) ──
    #pragma unroll
    for (int d = 1; d < 32; d <<= 1) {
        float pA = __shfl_up_sync(0xffffffffu, A,  d);
        float pB = __shfl_up_sync(0xffffffffu, Bz, d);
        float pD = __shfl_up_sync(0xffffffffu, D,  d);
        float pF = __shfl_up_sync(0xffffffffu, F,  d);
        if (lane >= d) {
            bool  nzm = (A != 1.0f);
            float Cm  = nzm ? A * kc : 0.0f;
            float Em  = nzm ? 0.0f : 1.0f;
            Bz = fmaf(A, pB, Bz);
            D  = fmaf(A, pD, fmaf(Cm, pF, D));
            F  = fmaf(Em, pF, F);
            A  = A * pA;
        }
    }

    // lower warp publishes its inclusive total
    if (half == 0 && lane == 31) {
        swtot[0] = A; swtot[1] = Bz; swtot[2] = D; swtot[3] = F;
    }

    __syncthreads();

    // upper warp composes with lower-warp total (lower applied first)
    if (half == 1) {
        float pA = swtot[0], pB = swtot[1], pD = swtot[2], pF = swtot[3];
        bool  nzm = (A != 1.0f);
        float Cm  = nzm ? A * kc : 0.0f;
        float Em  = nzm ? 0.0f : 1.0f;
        Bz = fmaf(A, pB, Bz);
        D  = fmaf(A, pD, fmaf(Cm, pF, D));
        F  = fmaf(Em, pF, F);
        A  = A * pA;
    }

    // apply INCLUSIVE map (segments 0..tx) to the initial state; this is
    // the initial state of segment tx+1. Thread 63 handles segment 0 with
    // the raw initial state.
    float Z, V, q;
    {
        bool  anyNz = (A != 1.0f);
        float C = anyNz ? A * kc : 0.0f;
        float E = anyNz ? 0.0f : 1.0f;
        Z = fmaf(A, Zi, Bz);
        V = fmaf(A, Vi, fmaf(C, qi, D));
        q = fmaf(E, qi, F);
        if (tx == SEGS - 1) { Z = Zi; V = Vi; q = qi; }
    }

    int r = (tx + 1) & (SEGS - 1);     // segment this thread replays

    // ── 4. replay segment r, write out in place ──
    {
        float4* seg4 = &sx[r * S4];
        #pragma unroll
        for (int i = 0; i < 8; i++) {
            float4 v = seg4[i];
            float xv[4] = {v.x, v.y, v.z, v.w};
            float ov[4];
            #pragma unroll
            for (int j = 0; j < 4; j++) {
                float xt  = xv[j];
                float nzf = fminf(xt, 1.0f);
                float anz = a * nzf;
                float ez  = 1.0f - nzf;
                Z = fmaf(anz, xt - Z, Z);
                V = fmaf(anz, q  - V, V);
                q = fmaf(ez, q, 1.0f);
                ov[j] = __fdividef(Z, V);
            }
            seg4[i] = make_float4(ov[0], ov[1], ov[2], ov[3]);
        }
    }

    __syncthreads();

    // ── 5. coalesced store ──
    {
        float4* gout = reinterpret_cast<float4*>(out + (size_t)b * T_LEN);
        #pragma unroll
        for (int i = 0; i < 8; i++) {
            int p = i * THREADS + tx;
            gout[p] = sx[p + (p >> 3)];
        }
    }
}

extern "C" void kernel_launch(void* const* d_in, const int* in_sizes, int n_in,
                              void* d_out, int out_size)
{
    const float* x     = (const float*)d_in[0];
    const float* alpha = (const float*)d_in[1];
    const float* Z0    = (const float*)d_in[2];
    const float* V0    = (const float*)d_in[3];
    const float* q0    = (const float*)d_in[4];
    float* out = (float*)d_out;

    croston_fused_kernel<<<B_ROWS, THREADS>>>(x, alpha, Z0, V0, q0, out);
}